// round 10
// baseline (speedup 1.0000x reference)
#include <cuda_runtime.h>
#include <math.h>
#include <stdint.h>

#define NN 100000
#define DD 128
#define CC 16
#define SS 16
#define KK 64
#define NIT 4
#define BMW 3125          // bitmap words for 100000 bits
#define HSZ 4096          // hash slots
#define NB  148           // persistent blocks (1 per SM -> all resident, barrier-safe)
#define KNOWN 0x80000000u

// ---------------- persistent device state (reset every launch) ----------------
__device__ unsigned int        g_nbr[NN];      // bits 0..15 class mask, bit31 = known
__device__ float               g_hx[CC * DD];
__device__ float               g_hxn[CC * DD];
__device__ int                 g_last[CC * KK];
__device__ int                 g_candCnt[CC];
__device__ unsigned int        g_barCount;
__device__ unsigned long long  g_candKeys[(size_t)CC * NN];

// ---------------- helpers ----------------
__device__ __forceinline__ unsigned ford(float f) {
    unsigned u = __float_as_uint(f);
    return (u >> 31) ? ~u : (u | 0x80000000u);
}
__device__ __forceinline__ float iford(unsigned u) {
    unsigned v = (u >> 31) ? (u & 0x7FFFFFFFu) : ~u;
    return __uint_as_float(v);
}
__device__ __forceinline__ int hslot(unsigned v) {
    return (int)((v * 2654435761u) >> 20);
}
// grid-wide barrier: monotonically increasing target (blocks * #barriers-so-far)
__device__ __forceinline__ void gridsync(unsigned target) {
    __syncthreads();
    if (threadIdx.x == 0) {
        __threadfence();                      // release
        atomicAdd(&g_barCount, 1u);
        while (*((volatile unsigned*)&g_barCount) < target) __nanosleep(64);
        __threadfence();                      // acquire
    }
    __syncthreads();
}

// ---------------- init (separate tiny launch) ----------------
__global__ void k_init() {
    int stride = gridDim.x * blockDim.x;
    int gt = blockIdx.x * blockDim.x + threadIdx.x;
    for (int v = gt; v < NN; v += stride) g_nbr[v] = 0u;
    if (gt < CC) g_candCnt[gt] = 0;
    if (gt == 0) g_barCount = 0u;
}

// ---------------- the persistent kernel ----------------
__global__ void __launch_bounds__(1024) k_main(
        const float* __restrict__ es, const float* __restrict__ W,
        const int* __restrict__ seeds,
        const int* __restrict__ src, const int* __restrict__ dst, int e,
        float* __restrict__ outP, float* __restrict__ outE,
        float* __restrict__ outHxes) {
    __shared__ __align__(16) unsigned char s_raw[45312];
    const int tid = threadIdx.x;
    const int bid = blockIdx.x;
    const int lane = tid & 31;
    unsigned bargen = 0;

    for (int t = 0; t < NIT; t++) {
        const int per = (t == 0) ? SS : KK;
        const int nm = CC * per;

        // ================= PHASE A: memory (blocks 0..15) | edges (16..147) =========
        if (bid >= CC) {
            unsigned* bm    = reinterpret_cast<unsigned*>(s_raw);
            unsigned* hkey  = reinterpret_cast<unsigned*>(s_raw + 12512);
            unsigned* hmask = reinterpret_cast<unsigned*>(s_raw + 12512 + 16384);
            const int b2 = bid - CC;

            for (int i = tid; i < BMW; i += 1024) bm[i] = 0u;
            for (int i = tid; i < HSZ; i += 1024) { hkey[i] = 0u; hmask[i] = 0u; }
            __syncthreads();
            if (tid < nm) {
                int m = tid;
                unsigned u = (unsigned)((t == 0) ? seeds[m] : __ldcg(&g_last[m]));
                unsigned bit = 1u << (m / per);
                atomicOr(&bm[u >> 5], 1u << (u & 31));
                int s = hslot(u);
                for (;;) {
                    unsigned k = atomicCAS(&hkey[s], 0u, u + 1u);
                    if (k == 0u || k == u + 1u) { atomicOr(&hmask[s], bit); break; }
                    s = (s + 1) & (HSZ - 1);
                }
                if (b2 == 0) atomicOr(&g_nbr[u], KNOWN); // promote to known
            }
            __syncthreads();

            const int e4 = e >> 2;
            const int4* s4 = reinterpret_cast<const int4*>(src);
            const int stride = (NB - CC) * 1024;
            for (int i = b2 * 1024 + tid; i < e4; i += stride) {
                int4 s = s4[i];
#pragma unroll
                for (int q = 0; q < 4; q++) {
                    unsigned u = (unsigned)((q == 0) ? s.x : (q == 1) ? s.y : (q == 2) ? s.z : s.w);
                    if ((bm[u >> 5] >> (u & 31)) & 1u) {
                        int sl = hslot(u);
                        unsigned m;
                        for (;;) {
                            unsigned k = hkey[sl];
                            if (k == u + 1u) { m = hmask[sl]; break; }
                            sl = (sl + 1) & (HSZ - 1);
                        }
                        atomicOr(&g_nbr[dst[4 * i + q]], m);
                    }
                }
            }
            int tail = e & 3, tb = e - tail;
            if (b2 == 0 && tid < tail) {
                unsigned u = (unsigned)src[tb + tid];
                if ((bm[u >> 5] >> (u & 31)) & 1u) {
                    int sl = hslot(u);
                    unsigned m;
                    for (;;) {
                        unsigned k = hkey[sl];
                        if (k == u + 1u) { m = hmask[sl]; break; }
                        sl = (sl + 1) & (HSZ - 1);
                    }
                    atomicOr(&g_nbr[dst[tb + tid]], m);
                }
            }
        } else {
            // ---------- memory role: block c, 1024 threads in 8 groups ----------
            float* s_inp  = reinterpret_cast<float*>(s_raw);              // 32768
            float* s_part = reinterpret_cast<float*>(s_raw + 32768);      // 4096
            float* s_q    = reinterpret_cast<float*>(s_raw + 36864);      // 512
            float* s_a    = reinterpret_cast<float*>(s_raw + 37376);      // 256
            float* s_pre  = reinterpret_cast<float*>(s_raw + 37632);      // 512
            float* s_red  = reinterpret_cast<float*>(s_raw + 38144);      // 64

            const int c = bid;
            const int g = tid >> 7;      // 0..7
            const int d = tid & 127;
            const int kk = per;

            for (int j = g; j < kk; j += 8) {
                int node = (t == 0) ? seeds[c * kk + j] : __ldcg(&g_last[c * KK + j]);
                s_inp[j * DD + d] = es[(size_t)node * DD + d];
            }
            if (t == 0) {
                float part = 0.0f;
                for (int j = g; j < kk; j += 8) part += s_inp[j * DD + d];
                s_part[g * DD + d] = part;
                __syncthreads();
                if (g == 0) {
                    float s = 0.0f;
#pragma unroll
                    for (int i = 0; i < 8; i++) s += s_part[i * DD + d];
                    s_q[d] = s / (float)kk;
                }
            } else {
                if (g == 0) s_q[d] = g_hx[c * DD + d];
            }
            __syncthreads();

            // logits: warp jw handles rows jw, jw+32
            int jw = tid >> 5;
            for (int j = jw; j < kk; j += 32) {
                float p = 0.0f;
#pragma unroll
                for (int q = 0; q < 4; q++) {
                    int dd = lane + 32 * q;
                    p += s_inp[j * DD + dd] * s_q[dd];
                }
#pragma unroll
                for (int o = 16; o; o >>= 1) p += __shfl_xor_sync(0xffffffffu, p, o);
                if (lane == 0) s_a[j] = p / sqrtf(128.0f);
            }
            __syncthreads();
            if (tid < 32) {
                float a0 = (tid < kk) ? s_a[tid] : -1e30f;
                float a1 = (tid + 32 < kk) ? s_a[tid + 32] : -1e30f;
                float m = fmaxf(a0, a1);
#pragma unroll
                for (int o = 16; o; o >>= 1) m = fmaxf(m, __shfl_xor_sync(0xffffffffu, m, o));
                float e0 = (tid < kk) ? expf(a0 - m) : 0.0f;
                float e1 = (tid + 32 < kk) ? expf(a1 - m) : 0.0f;
                float s = e0 + e1;
#pragma unroll
                for (int o = 16; o; o >>= 1) s += __shfl_xor_sync(0xffffffffu, s, o);
                if (tid < kk) s_a[tid] = e0 / s;
                if (tid + 32 < kk) s_a[tid + 32] = e1 / s;
            }
            __syncthreads();
            {
                float part = 0.0f;
                for (int j = g; j < kk; j += 8) part += s_a[j] * s_inp[j * DD + d];
                s_part[g * DD + d] = part;
            }
            __syncthreads();
            if (g == 0) {
                float ctx = 0.0f;
#pragma unroll
                for (int i = 0; i < 8; i++) ctx += s_part[i * DD + d];
                s_pre[d] = ctx + ((t > 0) ? s_q[d] : 0.0f);
            }
            __syncthreads();
            {
                float part = 0.0f;
                const int i0 = g * 16;
#pragma unroll 4
                for (int i = i0; i < i0 + 16; i++) part += s_pre[i] * W[i * DD + d];
                s_part[g * DD + d] = part;
            }
            __syncthreads();
            float h = 0.0f;
            if (g == 0) {
                float acc = 0.0f;
#pragma unroll
                for (int i = 0; i < 8; i++) acc += s_part[i * DD + d];
                h = tanhf(acc);
                g_hx[c * DD + d] = h;
                outHxes[(t * CC + c) * DD + d] = h;
                float ss = h * h;
#pragma unroll
                for (int o = 16; o; o >>= 1) ss += __shfl_xor_sync(0xffffffffu, ss, o);
                if (lane == 0) s_red[tid >> 5] = ss;
            }
            __syncthreads();
            if (g == 0) {
                float ns = s_red[0] + s_red[1] + s_red[2] + s_red[3];
                g_hxn[c * DD + d] = h / (sqrtf(ns) + 1e-8f);
            }
        }

        bargen += NB; gridsync(bargen);

        // ================= PHASE B: compact (all blocks) =============================
        {
            float* sh = reinterpret_cast<float*>(s_raw);  // 8 KB hxn stage
            for (int i = tid; i < CC * DD; i += 1024) sh[i] = __ldcg(&g_hxn[i]);
            __syncthreads();
            int v = bid * 1024 + tid; // NB*1024 = 151552 >= NN
            unsigned m = 0u;
            if (v < NN) {
                m = __ldcg(&g_nbr[v]);
                if (m & KNOWN) m = 0u;
                else m &= 0xFFFFu;
            }
            unsigned ball = __ballot_sync(0xffffffffu, m != 0u);
            while (ball) {
                int L = __ffs(ball) - 1;
                ball &= ball - 1;
                int vv = __shfl_sync(0xffffffffu, v, L);
                unsigned mm = __shfl_sync(0xffffffffu, m, L);
                const float4 r = reinterpret_cast<const float4*>(es)[(size_t)vv * 32 + lane];
                float ss = r.x * r.x + r.y * r.y + r.z * r.z + r.w * r.w;
#pragma unroll
                for (int o = 16; o; o >>= 1) ss += __shfl_xor_sync(0xffffffffu, ss, o);
                float inv = 1.0f / (sqrtf(ss) + 1e-8f);
                while (mm) {
                    int c2 = __ffs(mm) - 1;
                    mm &= mm - 1;
                    const float4 hh = reinterpret_cast<const float4*>(sh + c2 * DD)[lane];
                    float dp = r.x * hh.x + r.y * hh.y + r.z * hh.z + r.w * hh.w;
#pragma unroll
                    for (int o = 16; o; o >>= 1) dp += __shfl_xor_sync(0xffffffffu, dp, o);
                    if (lane == 0) {
                        float score = dp * inv;
                        unsigned long long key =
                            ((unsigned long long)ford(score) << 32) |
                            (unsigned long long)(0xFFFFFFFFu - (unsigned)vv);
                        int p = atomicAdd(&g_candCnt[c2], 1);
                        g_candKeys[(size_t)c2 * NN + p] = key;
                    }
                }
            }
        }

        bargen += NB; gridsync(bargen);

        // ================= PHASE C: topk (blocks 0..15) ==============================
        if (bid < CC) {
            unsigned* hist = reinterpret_cast<unsigned*>(s_raw);                 // 16384
            unsigned long long* sbuf = reinterpret_cast<unsigned long long*>(s_raw + 16384); // 4096
            unsigned* s_wsum = reinterpret_cast<unsigned*>(s_raw + 20480);       // 128
            int* s_sc = reinterpret_cast<int*>(s_raw + 20608);                   // s_b,s_cum,s_stop,s_scnt

            const int c = bid;
            const int wid = tid >> 5;
            const unsigned long long* keys = g_candKeys + (size_t)c * NN;
            int cnt = atomicAdd(&g_candCnt[c], 0);
            __syncthreads();
            if (tid == 0) atomicExch(&g_candCnt[c], 0); // reset for next iteration
            int r = cnt < KK ? cnt : KK;

            unsigned long long prefix = 0ULL;
            int sf = 64;
            if (cnt > 512) {
                int rr = r;
                for (int shift = 52; shift >= 4; shift -= 12) {
                    for (int j = tid; j < 4096; j += 1024) hist[j] = 0u;
                    __syncthreads();
                    for (int i = tid; i < cnt; i += 1024) {
                        unsigned long long key = __ldcg(&keys[i]);
                        if (sf >= 64 || (key >> sf) == prefix)
                            atomicAdd(&hist[(unsigned)((key >> shift) & 0xFFFULL)], 1u);
                    }
                    __syncthreads();
                    int b4 = tid * 4;
                    unsigned lsum = hist[b4] + hist[b4 + 1] + hist[b4 + 2] + hist[b4 + 3];
                    unsigned x = lsum;
#pragma unroll
                    for (int off = 1; off < 32; off <<= 1) {
                        unsigned y = __shfl_down_sync(0xffffffffu, x, off);
                        if (lane + off < 32) x += y;
                    }
                    if (lane == 0) s_wsum[wid] = x;
                    __syncthreads();
                    if (wid == 0) {
                        unsigned w = s_wsum[lane];
                        unsigned own = w;
#pragma unroll
                        for (int off = 1; off < 32; off <<= 1) {
                            unsigned y = __shfl_down_sync(0xffffffffu, w, off);
                            if (lane + off < 32) w += y;
                        }
                        s_wsum[lane] = w - own;
                    }
                    __syncthreads();
                    unsigned incl = x + s_wsum[wid];
                    unsigned above = incl - lsum;
                    if (above < (unsigned)rr && incl >= (unsigned)rr) {
                        unsigned cum = above;
                        for (int b = b4 + 3; b >= b4; --b) {
                            unsigned h2 = hist[b];
                            if (cum + h2 >= (unsigned)rr) {
                                s_sc[0] = b;
                                s_sc[1] = (int)cum;
                                int aboveTot = (r - rr) + (int)cum;
                                s_sc[2] = (aboveTot + (int)h2 <= 256) ? 1 : 0;
                                break;
                            }
                            cum += h2;
                        }
                    }
                    __syncthreads();
                    prefix = (prefix << 12) | (unsigned long long)s_sc[0];
                    rr -= s_sc[1];
                    sf = shift;
                    int stop = s_sc[2];
                    __syncthreads();
                    if (stop) break;
                }
            }
            if (tid == 0) s_sc[3] = 0;
            __syncthreads();
            for (int i = tid; i < cnt; i += 1024) {
                unsigned long long key = __ldcg(&keys[i]);
                bool take = (sf >= 64) || ((key >> sf) >= prefix);
                if (take) {
                    int p = atomicAdd(&s_sc[3], 1);
                    if (p < 512) sbuf[p] = key;
                }
            }
            __syncthreads();
            int sc = s_sc[3] < 512 ? s_sc[3] : 512;
            int n = (sc <= 256) ? 256 : 512;
            if (tid < n && tid >= sc) sbuf[tid] = 0ULL;
            __syncthreads();
            for (int kk2 = 2; kk2 <= n; kk2 <<= 1) {
                for (int j = kk2 >> 1; j > 0; j >>= 1) {
                    if (tid < n) {
                        int ixj = tid ^ j;
                        if (ixj > tid) {
                            unsigned long long a = sbuf[tid], b = sbuf[ixj];
                            bool desc = ((tid & kk2) == 0);
                            if (desc ? (a < b) : (a > b)) { sbuf[tid] = b; sbuf[ixj] = a; }
                        }
                    }
                    __syncthreads();
                }
            }
            const int base = (t * CC + c) * KK;
            if (tid < KK && tid < r) {
                unsigned long long key = sbuf[tid];
                int v = (int)(0xFFFFFFFFu - (unsigned)(key & 0xFFFFFFFFull));
                outP[base + tid] = iford((unsigned)(key >> 32));
                outE[base + tid] = (float)v;
                g_last[c * KK + tid] = v;
            }
            if (tid == 0 && r < KK) {
                int fill = r;
                for (int v = 0; v < NN && fill < KK; v++) {
                    unsigned m = __ldcg(&g_nbr[v]);
                    bool valid = (((m >> c) & 1u) != 0u) && !(m & KNOWN);
                    if (!valid) {
                        outP[base + fill] = -1e9f;
                        outE[base + fill] = (float)v;
                        g_last[c * KK + fill] = v;
                        fill++;
                    }
                }
            }
        }

        if (t < NIT - 1) { bargen += NB; gridsync(bargen); }
    }
}

// ---------------- launch ----------------
extern "C" void kernel_launch(void* const* d_in, const int* in_sizes, int n_in,
                              void* d_out, int out_size) {
    const float* es    = (const float*)d_in[0];
    const int*   edges = (const int*)d_in[1];
    const int*   seeds = (const int*)d_in[2];
    const float* W     = (const float*)d_in[3];
    (void)n_in; (void)out_size;

    int e = in_sizes[1] / 2;
    const int* src = edges;
    const int* dst = edges + e;

    float* out  = (float*)d_out;
    float* outP = out;
    float* outE = out + NIT * CC * KK;
    float* outH = out + 2 * NIT * CC * KK;

    k_init<<<128, 256>>>();
    k_main<<<NB, 1024>>>(es, W, seeds, src, dst, e, outP, outE, outH);
}

// round 11
// speedup vs baseline: 1.2885x; 1.2885x over previous
#include <cuda_runtime.h>
#include <math.h>
#include <stdint.h>

#define NN 100000
#define DD 128
#define CC 16
#define SS 16
#define KK 64
#define NIT 4
#define BMW 3125          // bitmap words for 100000 bits
#define HSZ 4096          // hash slots
#define NB  148           // persistent blocks (1 per SM -> all resident, barrier-safe)
#define KNOWN 0x80000000u

// ---------------- persistent device state (reset every launch) ----------------
__device__ unsigned int        g_nbr[NN];      // bits 0..15 class mask, bit31 = known
__device__ float               g_hx[CC * DD];
__device__ float               g_hxn[CC * DD];
__device__ int                 g_last[CC * KK];
__device__ int                 g_candCnt[CC];
__device__ int                 g_clistCnt;
__device__ unsigned int        g_barCount;
__device__ unsigned int        g_clist[(size_t)CC * NN];       // (c<<17)|v pairs
__device__ unsigned long long  g_candKeys[(size_t)CC * NN];

// ---------------- helpers ----------------
__device__ __forceinline__ unsigned ford(float f) {
    unsigned u = __float_as_uint(f);
    return (u >> 31) ? ~u : (u | 0x80000000u);
}
__device__ __forceinline__ float iford(unsigned u) {
    unsigned v = (u >> 31) ? (u & 0x7FFFFFFFu) : ~u;
    return __uint_as_float(v);
}
__device__ __forceinline__ int hslot(unsigned v) {
    return (int)((v * 2654435761u) >> 20);
}
__device__ __forceinline__ void gridsync(unsigned target) {
    __syncthreads();
    if (threadIdx.x == 0) {
        __threadfence();
        atomicAdd(&g_barCount, 1u);
        while (*((volatile unsigned*)&g_barCount) < target) __nanosleep(64);
        __threadfence();
    }
    __syncthreads();
}

// ---------------- init (separate tiny launch) ----------------
__global__ void k_init() {
    int stride = gridDim.x * blockDim.x;
    int gt = blockIdx.x * blockDim.x + threadIdx.x;
    for (int v = gt; v < NN; v += stride) g_nbr[v] = 0u;
    if (gt < CC) g_candCnt[gt] = 0;
    if (gt == 0) { g_barCount = 0u; g_clistCnt = 0; }
}

// ---------------- the persistent kernel ----------------
__global__ void __launch_bounds__(1024) k_main(
        const float* __restrict__ es, const float* __restrict__ W,
        const int* __restrict__ seeds,
        const int* __restrict__ src, const int* __restrict__ dst, int e,
        float* __restrict__ outP, float* __restrict__ outE,
        float* __restrict__ outHxes) {
    __shared__ __align__(16) unsigned char s_raw[45312];
    const int tid = threadIdx.x;
    const int bid = blockIdx.x;
    const int lane = tid & 31;
    unsigned bargen = 0;

    for (int t = 0; t < NIT; t++) {
        const int per = (t == 0) ? SS : KK;
        const int nm = CC * per;

        // ================= PHASE A: memory (blocks 0..15) | edges (16..147) =========
        if (bid >= CC) {
            unsigned* bm    = reinterpret_cast<unsigned*>(s_raw);
            unsigned* hkey  = reinterpret_cast<unsigned*>(s_raw + 12512);
            unsigned* hmask = reinterpret_cast<unsigned*>(s_raw + 12512 + 16384);
            const int b2 = bid - CC;

            for (int i = tid; i < BMW; i += 1024) bm[i] = 0u;
            for (int i = tid; i < HSZ; i += 1024) { hkey[i] = 0u; hmask[i] = 0u; }
            __syncthreads();
            if (tid < nm) {
                int m = tid;
                unsigned u = (unsigned)((t == 0) ? seeds[m] : __ldcg(&g_last[m]));
                unsigned bit = 1u << (m / per);
                atomicOr(&bm[u >> 5], 1u << (u & 31));
                int s = hslot(u);
                for (;;) {
                    unsigned k = atomicCAS(&hkey[s], 0u, u + 1u);
                    if (k == 0u || k == u + 1u) { atomicOr(&hmask[s], bit); break; }
                    s = (s + 1) & (HSZ - 1);
                }
                if (b2 == 0) atomicOr(&g_nbr[u], KNOWN);
            }
            __syncthreads();

            const int e4 = e >> 2;
            const int4* s4 = reinterpret_cast<const int4*>(src);
            const int stride = (NB - CC) * 1024;
#pragma unroll 4
            for (int i = b2 * 1024 + tid; i < e4; i += stride) {
                int4 s = s4[i];
#pragma unroll
                for (int q = 0; q < 4; q++) {
                    unsigned u = (unsigned)((q == 0) ? s.x : (q == 1) ? s.y : (q == 2) ? s.z : s.w);
                    if ((bm[u >> 5] >> (u & 31)) & 1u) {
                        int sl = hslot(u);
                        unsigned m;
                        for (;;) {
                            unsigned k = hkey[sl];
                            if (k == u + 1u) { m = hmask[sl]; break; }
                            sl = (sl + 1) & (HSZ - 1);
                        }
                        atomicOr(&g_nbr[dst[4 * i + q]], m);
                    }
                }
            }
            int tail = e & 3, tb = e - tail;
            if (b2 == 0 && tid < tail) {
                unsigned u = (unsigned)src[tb + tid];
                if ((bm[u >> 5] >> (u & 31)) & 1u) {
                    int sl = hslot(u);
                    unsigned m;
                    for (;;) {
                        unsigned k = hkey[sl];
                        if (k == u + 1u) { m = hmask[sl]; break; }
                        sl = (sl + 1) & (HSZ - 1);
                    }
                    atomicOr(&g_nbr[dst[tb + tid]], m);
                }
            }
        } else {
            // ---------- memory role ----------
            float* s_inp  = reinterpret_cast<float*>(s_raw);              // 32768
            float* s_part = reinterpret_cast<float*>(s_raw + 32768);      // 4096
            float* s_q    = reinterpret_cast<float*>(s_raw + 36864);      // 512
            float* s_a    = reinterpret_cast<float*>(s_raw + 37376);      // 256
            float* s_pre  = reinterpret_cast<float*>(s_raw + 37632);      // 512
            float* s_red  = reinterpret_cast<float*>(s_raw + 38144);      // 64

            const int c = bid;
            const int g = tid >> 7;
            const int d = tid & 127;
            const int kk = per;

            for (int j = g; j < kk; j += 8) {
                int node = (t == 0) ? seeds[c * kk + j] : __ldcg(&g_last[c * KK + j]);
                s_inp[j * DD + d] = es[(size_t)node * DD + d];
            }
            if (t == 0) {
                float part = 0.0f;
                for (int j = g; j < kk; j += 8) part += s_inp[j * DD + d];
                s_part[g * DD + d] = part;
                __syncthreads();
                if (g == 0) {
                    float s = 0.0f;
#pragma unroll
                    for (int i = 0; i < 8; i++) s += s_part[i * DD + d];
                    s_q[d] = s / (float)kk;
                }
            } else {
                if (g == 0) s_q[d] = g_hx[c * DD + d];
            }
            __syncthreads();

            int jw = tid >> 5;
            for (int j = jw; j < kk; j += 32) {
                float p = 0.0f;
#pragma unroll
                for (int q = 0; q < 4; q++) {
                    int dd = lane + 32 * q;
                    p += s_inp[j * DD + dd] * s_q[dd];
                }
#pragma unroll
                for (int o = 16; o; o >>= 1) p += __shfl_xor_sync(0xffffffffu, p, o);
                if (lane == 0) s_a[j] = p / sqrtf(128.0f);
            }
            __syncthreads();
            if (tid < 32) {
                float a0 = (tid < kk) ? s_a[tid] : -1e30f;
                float a1 = (tid + 32 < kk) ? s_a[tid + 32] : -1e30f;
                float m = fmaxf(a0, a1);
#pragma unroll
                for (int o = 16; o; o >>= 1) m = fmaxf(m, __shfl_xor_sync(0xffffffffu, m, o));
                float e0 = (tid < kk) ? expf(a0 - m) : 0.0f;
                float e1 = (tid + 32 < kk) ? expf(a1 - m) : 0.0f;
                float s = e0 + e1;
#pragma unroll
                for (int o = 16; o; o >>= 1) s += __shfl_xor_sync(0xffffffffu, s, o);
                if (tid < kk) s_a[tid] = e0 / s;
                if (tid + 32 < kk) s_a[tid + 32] = e1 / s;
            }
            __syncthreads();
            {
                float part = 0.0f;
                for (int j = g; j < kk; j += 8) part += s_a[j] * s_inp[j * DD + d];
                s_part[g * DD + d] = part;
            }
            __syncthreads();
            if (g == 0) {
                float ctx = 0.0f;
#pragma unroll
                for (int i = 0; i < 8; i++) ctx += s_part[i * DD + d];
                s_pre[d] = ctx + ((t > 0) ? s_q[d] : 0.0f);
            }
            __syncthreads();
            {
                float part = 0.0f;
                const int i0 = g * 16;
#pragma unroll 4
                for (int i = i0; i < i0 + 16; i++) part += s_pre[i] * W[i * DD + d];
                s_part[g * DD + d] = part;
            }
            __syncthreads();
            float h = 0.0f;
            if (g == 0) {
                float acc = 0.0f;
#pragma unroll
                for (int i = 0; i < 8; i++) acc += s_part[i * DD + d];
                h = tanhf(acc);
                g_hx[c * DD + d] = h;
                outHxes[(t * CC + c) * DD + d] = h;
                float ss = h * h;
#pragma unroll
                for (int o = 16; o; o >>= 1) ss += __shfl_xor_sync(0xffffffffu, ss, o);
                if (lane == 0) s_red[tid >> 5] = ss;
            }
            __syncthreads();
            if (g == 0) {
                float ns = s_red[0] + s_red[1] + s_red[2] + s_red[3];
                g_hxn[c * DD + d] = h / (sqrtf(ns) + 1e-8f);
            }
        }

        bargen += NB; gridsync(bargen);

        // ================= PHASE B1: compact candidate (c,v) pairs to global list ====
        {
            int v = bid * 1024 + tid;
            unsigned m = 0u;
            if (v < NN) {
                m = __ldcg(&g_nbr[v]);
                m = (m & KNOWN) ? 0u : (m & 0xFFFFu);
            }
            int pc = __popc(m);
            int x = pc;
#pragma unroll
            for (int o = 1; o < 32; o <<= 1) {
                int y = __shfl_up_sync(0xffffffffu, x, o);
                if (lane >= o) x += y;
            }
            int wtot = __shfl_sync(0xffffffffu, x, 31);
            int excl = x - pc;
            int basep = 0;
            if (lane == 31 && wtot) basep = atomicAdd(&g_clistCnt, wtot);
            basep = __shfl_sync(0xffffffffu, basep, 31);
            int p = basep + excl;
            while (m) {
                int c2 = __ffs(m) - 1;
                m &= m - 1;
                g_clist[p++] = ((unsigned)c2 << 17) | (unsigned)v;
            }
        }

        bargen += NB; gridsync(bargen);

        // ================= PHASE B2: score list entries, 4-wide pipelined ============
        {
            float* sh = reinterpret_cast<float*>(s_raw);
            for (int i = tid; i < CC * DD; i += 1024) sh[i] = __ldcg(&g_hxn[i]);
            __syncthreads();
            const float4* sh4 = reinterpret_cast<const float4*>(sh);
            const float4* es4 = reinterpret_cast<const float4*>(es);
            const int total = *((volatile int*)&g_clistCnt);
            const int gw = (bid * 1024 + tid) >> 5;
            const int nwarp = NB * 32;
            for (int base = gw * 4; base < total; base += nwarp * 4) {
                int n = total - base; if (n > 4) n = 4;
                float ssum[4], dsum[4];
                unsigned ev[4];
#pragma unroll
                for (int k = 0; k < 4; k++) {
                    ssum[k] = 0.0f; dsum[k] = 0.0f; ev[k] = 0u;
                    if (k < n) {
                        unsigned ent = __ldcg(&g_clist[base + k]);
                        ev[k] = ent;
                        unsigned v = ent & 0x1FFFFu;
                        unsigned c2 = ent >> 17;
                        const float4 r = es4[(size_t)v * 32 + lane];
                        const float4 h = sh4[c2 * 32 + lane];
                        ssum[k] = r.x * r.x + r.y * r.y + r.z * r.z + r.w * r.w;
                        dsum[k] = r.x * h.x + r.y * h.y + r.z * h.z + r.w * h.w;
                    }
                }
#pragma unroll
                for (int k = 0; k < 4; k++) {
#pragma unroll
                    for (int o = 16; o; o >>= 1) {
                        ssum[k] += __shfl_xor_sync(0xffffffffu, ssum[k], o);
                        dsum[k] += __shfl_xor_sync(0xffffffffu, dsum[k], o);
                    }
                }
                float sc0 = dsum[0] * (1.0f / (sqrtf(ssum[0]) + 1e-8f));
                float sc1 = dsum[1] * (1.0f / (sqrtf(ssum[1]) + 1e-8f));
                float sc2 = dsum[2] * (1.0f / (sqrtf(ssum[2]) + 1e-8f));
                float sc3 = dsum[3] * (1.0f / (sqrtf(ssum[3]) + 1e-8f));
                if (lane < n) {
                    float score = (lane == 0) ? sc0 : (lane == 1) ? sc1 : (lane == 2) ? sc2 : sc3;
                    unsigned ent = (lane == 0) ? ev[0] : (lane == 1) ? ev[1] : (lane == 2) ? ev[2] : ev[3];
                    unsigned v = ent & 0x1FFFFu;
                    int c2 = (int)(ent >> 17);
                    unsigned long long key =
                        ((unsigned long long)ford(score) << 32) |
                        (unsigned long long)(0xFFFFFFFFu - v);
                    int p = atomicAdd(&g_candCnt[c2], 1);
                    g_candKeys[(size_t)c2 * NN + p] = key;
                }
            }
        }

        bargen += NB; gridsync(bargen);

        // ================= PHASE C: topk (blocks 0..15) ==============================
        if (bid < CC) {
            unsigned* hist = reinterpret_cast<unsigned*>(s_raw);
            unsigned long long* sbuf = reinterpret_cast<unsigned long long*>(s_raw + 16384);
            unsigned* s_wsum = reinterpret_cast<unsigned*>(s_raw + 20480);
            int* s_sc = reinterpret_cast<int*>(s_raw + 20608);

            const int c = bid;
            const int wid = tid >> 5;
            const unsigned long long* keys = g_candKeys + (size_t)c * NN;
            int cnt = atomicAdd(&g_candCnt[c], 0);
            __syncthreads();
            if (tid == 0) atomicExch(&g_candCnt[c], 0);
            int r = cnt < KK ? cnt : KK;

            unsigned long long prefix = 0ULL;
            int sf = 64;
            if (cnt > 512) {
                int rr = r;
                for (int shift = 52; shift >= 4; shift -= 12) {
                    for (int j = tid; j < 4096; j += 1024) hist[j] = 0u;
                    __syncthreads();
                    for (int i = tid; i < cnt; i += 1024) {
                        unsigned long long key = __ldcg(&keys[i]);
                        if (sf >= 64 || (key >> sf) == prefix)
                            atomicAdd(&hist[(unsigned)((key >> shift) & 0xFFFULL)], 1u);
                    }
                    __syncthreads();
                    int b4 = tid * 4;
                    unsigned lsum = hist[b4] + hist[b4 + 1] + hist[b4 + 2] + hist[b4 + 3];
                    unsigned x = lsum;
#pragma unroll
                    for (int off = 1; off < 32; off <<= 1) {
                        unsigned y = __shfl_down_sync(0xffffffffu, x, off);
                        if (lane + off < 32) x += y;
                    }
                    if (lane == 0) s_wsum[wid] = x;
                    __syncthreads();
                    if (wid == 0) {
                        unsigned w = s_wsum[lane];
                        unsigned own = w;
#pragma unroll
                        for (int off = 1; off < 32; off <<= 1) {
                            unsigned y = __shfl_down_sync(0xffffffffu, w, off);
                            if (lane + off < 32) w += y;
                        }
                        s_wsum[lane] = w - own;
                    }
                    __syncthreads();
                    unsigned incl = x + s_wsum[wid];
                    unsigned above = incl - lsum;
                    if (above < (unsigned)rr && incl >= (unsigned)rr) {
                        unsigned cum = above;
                        for (int b = b4 + 3; b >= b4; --b) {
                            unsigned h2 = hist[b];
                            if (cum + h2 >= (unsigned)rr) {
                                s_sc[0] = b;
                                s_sc[1] = (int)cum;
                                int aboveTot = (r - rr) + (int)cum;
                                s_sc[2] = (aboveTot + (int)h2 <= 256) ? 1 : 0;
                                break;
                            }
                            cum += h2;
                        }
                    }
                    __syncthreads();
                    prefix = (prefix << 12) | (unsigned long long)s_sc[0];
                    rr -= s_sc[1];
                    sf = shift;
                    int stop = s_sc[2];
                    __syncthreads();
                    if (stop) break;
                }
            }
            if (tid == 0) s_sc[3] = 0;
            __syncthreads();
            for (int i = tid; i < cnt; i += 1024) {
                unsigned long long key = __ldcg(&keys[i]);
                bool take = (sf >= 64) || ((key >> sf) >= prefix);
                if (take) {
                    int p = atomicAdd(&s_sc[3], 1);
                    if (p < 512) sbuf[p] = key;
                }
            }
            __syncthreads();
            int sc = s_sc[3] < 512 ? s_sc[3] : 512;
            int n = (sc <= 256) ? 256 : 512;
            if (tid < n && tid >= sc) sbuf[tid] = 0ULL;
            __syncthreads();
            for (int kk2 = 2; kk2 <= n; kk2 <<= 1) {
                for (int j = kk2 >> 1; j > 0; j >>= 1) {
                    if (tid < n) {
                        int ixj = tid ^ j;
                        if (ixj > tid) {
                            unsigned long long a = sbuf[tid], b = sbuf[ixj];
                            bool desc = ((tid & kk2) == 0);
                            if (desc ? (a < b) : (a > b)) { sbuf[tid] = b; sbuf[ixj] = a; }
                        }
                    }
                    __syncthreads();
                }
            }
            const int base = (t * CC + c) * KK;
            if (tid < KK && tid < r) {
                unsigned long long key = sbuf[tid];
                int v = (int)(0xFFFFFFFFu - (unsigned)(key & 0xFFFFFFFFull));
                outP[base + tid] = iford((unsigned)(key >> 32));
                outE[base + tid] = (float)v;
                g_last[c * KK + tid] = v;
            }
            if (tid == 0 && r < KK) {
                int fill = r;
                for (int v = 0; v < NN && fill < KK; v++) {
                    unsigned m = __ldcg(&g_nbr[v]);
                    bool valid = (((m >> c) & 1u) != 0u) && !(m & KNOWN);
                    if (!valid) {
                        outP[base + fill] = -1e9f;
                        outE[base + fill] = (float)v;
                        g_last[c * KK + fill] = v;
                        fill++;
                    }
                }
            }
        } else if (bid == CC && tid == 0) {
            atomicExch(&g_clistCnt, 0);   // reset candidate list for next iteration
        }

        if (t < NIT - 1) { bargen += NB; gridsync(bargen); }
    }
}

// ---------------- launch ----------------
extern "C" void kernel_launch(void* const* d_in, const int* in_sizes, int n_in,
                              void* d_out, int out_size) {
    const float* es    = (const float*)d_in[0];
    const int*   edges = (const int*)d_in[1];
    const int*   seeds = (const int*)d_in[2];
    const float* W     = (const float*)d_in[3];
    (void)n_in; (void)out_size;

    int e = in_sizes[1] / 2;
    const int* src = edges;
    const int* dst = edges + e;

    float* out  = (float*)d_out;
    float* outP = out;
    float* outE = out + NIT * CC * KK;
    float* outH = out + 2 * NIT * CC * KK;

    k_init<<<128, 256>>>();
    k_main<<<NB, 1024>>>(es, W, seeds, src, dst, e, outP, outE, outH);
}

// round 12
// speedup vs baseline: 1.3162x; 1.0215x over previous
#include <cuda_runtime.h>
#include <math.h>
#include <stdint.h>

#define NN 100000
#define DD 128
#define CC 16
#define SS 16
#define KK 64
#define NIT 4
#define BMW 3125          // bitmap words for 100000 bits
#define HSZ 4096          // hash slots
#define NB  148           // persistent blocks (1 per SM -> all resident, barrier-safe)
#define KNOWN 0x80000000u

// ---------------- persistent device state (reset every launch) ----------------
__device__ unsigned int        g_nbr[NN];      // bits 0..15 class mask, bit31 = known
__device__ float               g_hx[CC * DD];
__device__ float               g_hxn[CC * DD];
__device__ int                 g_last[CC * KK];
__device__ int                 g_clistCnt;
__device__ unsigned int        g_barCount;
__device__ unsigned int        g_clist[(size_t)CC * NN];       // (c<<17)|v pairs
__device__ unsigned long long  g_candKeys[(size_t)CC * NN];    // flat keys, class in bits 24-27

// ---------------- helpers ----------------
__device__ __forceinline__ unsigned ford(float f) {
    unsigned u = __float_as_uint(f);
    return (u >> 31) ? ~u : (u | 0x80000000u);
}
__device__ __forceinline__ float iford(unsigned u) {
    unsigned v = (u >> 31) ? (u & 0x7FFFFFFFu) : ~u;
    return __uint_as_float(v);
}
__device__ __forceinline__ int hslot(unsigned v) {
    return (int)((v * 2654435761u) >> 20);
}
__device__ __forceinline__ void gridsync(unsigned target) {
    __syncthreads();
    if (threadIdx.x == 0) {
        __threadfence();
        atomicAdd(&g_barCount, 1u);
        while (*((volatile unsigned*)&g_barCount) < target) __nanosleep(64);
        __threadfence();
    }
    __syncthreads();
}

// ---------------- init (separate tiny launch) ----------------
__global__ void k_init() {
    int stride = gridDim.x * blockDim.x;
    int gt = blockIdx.x * blockDim.x + threadIdx.x;
    for (int v = gt; v < NN; v += stride) g_nbr[v] = 0u;
    if (gt == 0) { g_barCount = 0u; g_clistCnt = 0; }
}

// ---------------- the persistent kernel ----------------
__global__ void __launch_bounds__(1024) k_main(
        const float* __restrict__ es, const float* __restrict__ W,
        const int* __restrict__ seeds,
        const int* __restrict__ src, const int* __restrict__ dst, int e,
        float* __restrict__ outP, float* __restrict__ outE,
        float* __restrict__ outHxes) {
    __shared__ __align__(16) unsigned char s_raw[45312];
    const int tid = threadIdx.x;
    const int bid = blockIdx.x;
    const int lane = tid & 31;
    unsigned bargen = 0;

    for (int t = 0; t < NIT; t++) {
        const int per = (t == 0) ? SS : KK;
        const int nm = CC * per;

        // ================= PHASE A: memory (blocks 0..15) | edges (16..147) =========
        if (bid >= CC) {
            unsigned* bm    = reinterpret_cast<unsigned*>(s_raw);
            unsigned* hkey  = reinterpret_cast<unsigned*>(s_raw + 12512);
            unsigned* hmask = reinterpret_cast<unsigned*>(s_raw + 12512 + 16384);
            const int b2 = bid - CC;

            if (bid == CC && tid == 0) atomicExch(&g_clistCnt, 0); // reset for this iter's B1

            for (int i = tid; i < BMW; i += 1024) bm[i] = 0u;
            for (int i = tid; i < HSZ; i += 1024) { hkey[i] = 0u; hmask[i] = 0u; }
            __syncthreads();
            if (tid < nm) {
                int m = tid;
                unsigned u = (unsigned)((t == 0) ? seeds[m] : __ldcg(&g_last[m]));
                unsigned bit = 1u << (m / per);
                atomicOr(&bm[u >> 5], 1u << (u & 31));
                int s = hslot(u);
                for (;;) {
                    unsigned k = atomicCAS(&hkey[s], 0u, u + 1u);
                    if (k == 0u || k == u + 1u) { atomicOr(&hmask[s], bit); break; }
                    s = (s + 1) & (HSZ - 1);
                }
                if (b2 == 0) atomicOr(&g_nbr[u], KNOWN);
            }
            __syncthreads();

            const int e4 = e >> 2;
            const int4* s4 = reinterpret_cast<const int4*>(src);
            const int stride = (NB - CC) * 1024;
#pragma unroll 4
            for (int i = b2 * 1024 + tid; i < e4; i += stride) {
                int4 s = s4[i];
#pragma unroll
                for (int q = 0; q < 4; q++) {
                    unsigned u = (unsigned)((q == 0) ? s.x : (q == 1) ? s.y : (q == 2) ? s.z : s.w);
                    if ((bm[u >> 5] >> (u & 31)) & 1u) {
                        int sl = hslot(u);
                        unsigned m;
                        for (;;) {
                            unsigned k = hkey[sl];
                            if (k == u + 1u) { m = hmask[sl]; break; }
                            sl = (sl + 1) & (HSZ - 1);
                        }
                        atomicOr(&g_nbr[dst[4 * i + q]], m);
                    }
                }
            }
            int tail = e & 3, tb = e - tail;
            if (b2 == 0 && tid < tail) {
                unsigned u = (unsigned)src[tb + tid];
                if ((bm[u >> 5] >> (u & 31)) & 1u) {
                    int sl = hslot(u);
                    unsigned m;
                    for (;;) {
                        unsigned k = hkey[sl];
                        if (k == u + 1u) { m = hmask[sl]; break; }
                        sl = (sl + 1) & (HSZ - 1);
                    }
                    atomicOr(&g_nbr[dst[tb + tid]], m);
                }
            }
        } else {
            // ---------- memory role ----------
            float* s_inp  = reinterpret_cast<float*>(s_raw);              // 32768
            float* s_part = reinterpret_cast<float*>(s_raw + 32768);      // 4096
            float* s_q    = reinterpret_cast<float*>(s_raw + 36864);      // 512
            float* s_a    = reinterpret_cast<float*>(s_raw + 37376);      // 256
            float* s_pre  = reinterpret_cast<float*>(s_raw + 37632);      // 512
            float* s_red  = reinterpret_cast<float*>(s_raw + 38144);      // 64

            const int c = bid;
            const int g = tid >> 7;
            const int d = tid & 127;
            const int kk = per;

            for (int j = g; j < kk; j += 8) {
                int node = (t == 0) ? seeds[c * kk + j] : __ldcg(&g_last[c * KK + j]);
                s_inp[j * DD + d] = es[(size_t)node * DD + d];
            }
            if (t == 0) {
                float part = 0.0f;
                for (int j = g; j < kk; j += 8) part += s_inp[j * DD + d];
                s_part[g * DD + d] = part;
                __syncthreads();
                if (g == 0) {
                    float s = 0.0f;
#pragma unroll
                    for (int i = 0; i < 8; i++) s += s_part[i * DD + d];
                    s_q[d] = s / (float)kk;
                }
            } else {
                if (g == 0) s_q[d] = g_hx[c * DD + d];
            }
            __syncthreads();

            int jw = tid >> 5;
            for (int j = jw; j < kk; j += 32) {
                float p = 0.0f;
#pragma unroll
                for (int q = 0; q < 4; q++) {
                    int dd = lane + 32 * q;
                    p += s_inp[j * DD + dd] * s_q[dd];
                }
#pragma unroll
                for (int o = 16; o; o >>= 1) p += __shfl_xor_sync(0xffffffffu, p, o);
                if (lane == 0) s_a[j] = p / sqrtf(128.0f);
            }
            __syncthreads();
            if (tid < 32) {
                float a0 = (tid < kk) ? s_a[tid] : -1e30f;
                float a1 = (tid + 32 < kk) ? s_a[tid + 32] : -1e30f;
                float m = fmaxf(a0, a1);
#pragma unroll
                for (int o = 16; o; o >>= 1) m = fmaxf(m, __shfl_xor_sync(0xffffffffu, m, o));
                float e0 = (tid < kk) ? expf(a0 - m) : 0.0f;
                float e1 = (tid + 32 < kk) ? expf(a1 - m) : 0.0f;
                float s = e0 + e1;
#pragma unroll
                for (int o = 16; o; o >>= 1) s += __shfl_xor_sync(0xffffffffu, s, o);
                if (tid < kk) s_a[tid] = e0 / s;
                if (tid + 32 < kk) s_a[tid + 32] = e1 / s;
            }
            __syncthreads();
            {
                float part = 0.0f;
                for (int j = g; j < kk; j += 8) part += s_a[j] * s_inp[j * DD + d];
                s_part[g * DD + d] = part;
            }
            __syncthreads();
            if (g == 0) {
                float ctx = 0.0f;
#pragma unroll
                for (int i = 0; i < 8; i++) ctx += s_part[i * DD + d];
                s_pre[d] = ctx + ((t > 0) ? s_q[d] : 0.0f);
            }
            __syncthreads();
            {
                float part = 0.0f;
                const int i0 = g * 16;
#pragma unroll 4
                for (int i = i0; i < i0 + 16; i++) part += s_pre[i] * W[i * DD + d];
                s_part[g * DD + d] = part;
            }
            __syncthreads();
            float h = 0.0f;
            if (g == 0) {
                float acc = 0.0f;
#pragma unroll
                for (int i = 0; i < 8; i++) acc += s_part[i * DD + d];
                h = tanhf(acc);
                g_hx[c * DD + d] = h;
                outHxes[(t * CC + c) * DD + d] = h;
                float ss = h * h;
#pragma unroll
                for (int o = 16; o; o >>= 1) ss += __shfl_xor_sync(0xffffffffu, ss, o);
                if (lane == 0) s_red[tid >> 5] = ss;
            }
            __syncthreads();
            if (g == 0) {
                float ns = s_red[0] + s_red[1] + s_red[2] + s_red[3];
                g_hxn[c * DD + d] = h / (sqrtf(ns) + 1e-8f);
            }
        }

        bargen += NB; gridsync(bargen);

        // ================= PHASE B1: compact candidate (c,v) pairs (block-agg) =======
        {
            int* s_b = reinterpret_cast<int*>(s_raw);   // [0]=block count, [1]=block base
            if (tid == 0) { s_b[0] = 0; s_b[1] = 0; }
            __syncthreads();
            int v = bid * 1024 + tid;
            unsigned m = 0u;
            if (v < NN) {
                m = __ldcg(&g_nbr[v]);
                m = (m & KNOWN) ? 0u : (m & 0xFFFFu);
            }
            int pc = __popc(m);
            int x = pc;
#pragma unroll
            for (int o = 1; o < 32; o <<= 1) {
                int y = __shfl_up_sync(0xffffffffu, x, o);
                if (lane >= o) x += y;
            }
            int wtot = __shfl_sync(0xffffffffu, x, 31);
            int excl = x - pc;
            int woff = 0;
            if (lane == 31 && wtot) woff = atomicAdd(&s_b[0], wtot);
            woff = __shfl_sync(0xffffffffu, woff, 31);
            __syncthreads();
            if (tid == 0 && s_b[0]) s_b[1] = atomicAdd(&g_clistCnt, s_b[0]);
            __syncthreads();
            int p = s_b[1] + woff + excl;
            while (m) {
                int c2 = __ffs(m) - 1;
                m &= m - 1;
                g_clist[p++] = ((unsigned)c2 << 17) | (unsigned)v;
            }
        }

        bargen += NB; gridsync(bargen);

        // ================= PHASE B2: score entries, write keys at own index ==========
        {
            float* sh = reinterpret_cast<float*>(s_raw);
            for (int i = tid; i < CC * DD; i += 1024) sh[i] = __ldcg(&g_hxn[i]);
            __syncthreads();
            const float4* sh4 = reinterpret_cast<const float4*>(sh);
            const float4* es4 = reinterpret_cast<const float4*>(es);
            const int total = *((volatile int*)&g_clistCnt);
            const int gw = (bid * 1024 + tid) >> 5;
            const int nwarp = NB * 32;
            for (int base = gw * 4; base < total; base += nwarp * 4) {
                int n = total - base; if (n > 4) n = 4;
                float ssum[4], dsum[4];
                unsigned ev[4];
#pragma unroll
                for (int k = 0; k < 4; k++) {
                    ssum[k] = 0.0f; dsum[k] = 0.0f; ev[k] = 0u;
                    if (k < n) {
                        unsigned ent = __ldcg(&g_clist[base + k]);
                        ev[k] = ent;
                        unsigned v = ent & 0x1FFFFu;
                        unsigned c2 = ent >> 17;
                        const float4 r = es4[(size_t)v * 32 + lane];
                        const float4 h = sh4[c2 * 32 + lane];
                        ssum[k] = r.x * r.x + r.y * r.y + r.z * r.z + r.w * r.w;
                        dsum[k] = r.x * h.x + r.y * h.y + r.z * h.z + r.w * h.w;
                    }
                }
#pragma unroll
                for (int k = 0; k < 4; k++) {
#pragma unroll
                    for (int o = 16; o; o >>= 1) {
                        ssum[k] += __shfl_xor_sync(0xffffffffu, ssum[k], o);
                        dsum[k] += __shfl_xor_sync(0xffffffffu, dsum[k], o);
                    }
                }
                float sc0 = dsum[0] * (1.0f / (sqrtf(ssum[0]) + 1e-8f));
                float sc1 = dsum[1] * (1.0f / (sqrtf(ssum[1]) + 1e-8f));
                float sc2 = dsum[2] * (1.0f / (sqrtf(ssum[2]) + 1e-8f));
                float sc3 = dsum[3] * (1.0f / (sqrtf(ssum[3]) + 1e-8f));
                if (lane < n) {
                    float score = (lane == 0) ? sc0 : (lane == 1) ? sc1 : (lane == 2) ? sc2 : sc3;
                    unsigned ent = (lane == 0) ? ev[0] : (lane == 1) ? ev[1] : (lane == 2) ? ev[2] : ev[3];
                    unsigned v = ent & 0x1FFFFu;
                    unsigned c2 = ent >> 17;
                    unsigned lowfull = 0xFFFFFFFFu - v;              // bits 17..31 are 1
                    unsigned low = (lowfull & 0xF0FFFFFFu) | (c2 << 24); // class in bits 24-27
                    unsigned long long key =
                        ((unsigned long long)ford(score) << 32) | (unsigned long long)low;
                    g_candKeys[base + lane] = key;                   // no atomics
                }
            }
        }

        bargen += NB; gridsync(bargen);

        // ================= PHASE C: topk (blocks 0..15), flat-list class filter ======
        if (bid < CC) {
            unsigned* hist = reinterpret_cast<unsigned*>(s_raw);
            unsigned long long* sbuf = reinterpret_cast<unsigned long long*>(s_raw + 16384);
            unsigned* s_wsum = reinterpret_cast<unsigned*>(s_raw + 20480);
            int* s_sc = reinterpret_cast<int*>(s_raw + 20608); // b,cum,stop,scnt,cnt

            const int c = bid;
            const int wid = tid >> 5;
            const unsigned long long* keys = g_candKeys;
            const int total = *((volatile int*)&g_clistCnt);

            int cnt = 0, r = 0, rr = 0;
            unsigned long long prefix = 0ULL;
            int sf = 64;
            for (int shift = 52; shift >= 4; shift -= 12) {
                for (int j = tid; j < 4096; j += 1024) hist[j] = 0u;
                __syncthreads();
                for (int i = tid; i < total; i += 1024) {
                    unsigned long long key = __ldcg(&keys[i]);
                    if ((unsigned)((key >> 24) & 0xFULL) == (unsigned)c &&
                        (sf >= 64 || (key >> sf) == prefix))
                        atomicAdd(&hist[(unsigned)((key >> shift) & 0xFFFULL)], 1u);
                }
                __syncthreads();
                int b4 = tid * 4;
                unsigned lsum = hist[b4] + hist[b4 + 1] + hist[b4 + 2] + hist[b4 + 3];
                unsigned x = lsum;
#pragma unroll
                for (int off = 1; off < 32; off <<= 1) {
                    unsigned y = __shfl_down_sync(0xffffffffu, x, off);
                    if (lane + off < 32) x += y;
                }
                if (lane == 0) s_wsum[wid] = x;
                __syncthreads();
                if (wid == 0) {
                    unsigned w = s_wsum[lane];
                    unsigned own = w;
#pragma unroll
                    for (int off = 1; off < 32; off <<= 1) {
                        unsigned y = __shfl_down_sync(0xffffffffu, w, off);
                        if (lane + off < 32) w += y;
                    }
                    s_wsum[lane] = w - own;
                }
                __syncthreads();
                unsigned incl = x + s_wsum[wid];
                unsigned above = incl - lsum;
                if (shift == 52) {
                    if (tid == 0) s_sc[4] = (int)incl; // total class-c count
                }
                __syncthreads();
                if (shift == 52) {
                    cnt = s_sc[4];
                    r = cnt < KK ? cnt : KK;
                    rr = r;
                    if (cnt <= 512) break;             // sf stays 64 -> collect all
                }
                if (above < (unsigned)rr && incl >= (unsigned)rr) {
                    unsigned cum = above;
                    for (int b = b4 + 3; b >= b4; --b) {
                        unsigned h2 = hist[b];
                        if (cum + h2 >= (unsigned)rr) {
                            s_sc[0] = b;
                            s_sc[1] = (int)cum;
                            int aboveTot = (r - rr) + (int)cum;
                            s_sc[2] = (aboveTot + (int)h2 <= 256) ? 1 : 0;
                            break;
                        }
                        cum += h2;
                    }
                }
                __syncthreads();
                prefix = (prefix << 12) | (unsigned long long)s_sc[0];
                rr -= s_sc[1];
                sf = shift;
                int stop = s_sc[2];
                __syncthreads();
                if (stop) break;
            }
            if (tid == 0) s_sc[3] = 0;
            __syncthreads();
            for (int i = tid; i < total; i += 1024) {
                unsigned long long key = __ldcg(&keys[i]);
                bool take = ((unsigned)((key >> 24) & 0xFULL) == (unsigned)c) &&
                            ((sf >= 64) || ((key >> sf) >= prefix));
                if (take) {
                    int p = atomicAdd(&s_sc[3], 1);
                    if (p < 512) sbuf[p] = key;
                }
            }
            __syncthreads();
            int sc = s_sc[3] < 512 ? s_sc[3] : 512;
            int n = (sc <= 256) ? 256 : 512;
            if (tid < n && tid >= sc) sbuf[tid] = 0ULL;
            __syncthreads();
            for (int kk2 = 2; kk2 <= n; kk2 <<= 1) {
                for (int j = kk2 >> 1; j > 0; j >>= 1) {
                    if (tid < n) {
                        int ixj = tid ^ j;
                        if (ixj > tid) {
                            unsigned long long a = sbuf[tid], b = sbuf[ixj];
                            bool desc = ((tid & kk2) == 0);
                            if (desc ? (a < b) : (a > b)) { sbuf[tid] = b; sbuf[ixj] = a; }
                        }
                    }
                    __syncthreads();
                }
            }
            const int base = (t * CC + c) * KK;
            if (tid < KK && tid < r) {
                unsigned long long key = sbuf[tid];
                unsigned low = (unsigned)(key & 0xFFFFFFFFull);
                unsigned vlow = low | 0x0F000000u;        // restore masked class bits
                int v = (int)(0xFFFFFFFFu - vlow);
                outP[base + tid] = iford((unsigned)(key >> 32));
                outE[base + tid] = (float)v;
                g_last[c * KK + tid] = v;
            }
            if (tid == 0 && r < KK) {
                int fill = r;
                for (int v = 0; v < NN && fill < KK; v++) {
                    unsigned m = __ldcg(&g_nbr[v]);
                    bool valid = (((m >> c) & 1u) != 0u) && !(m & KNOWN);
                    if (!valid) {
                        outP[base + fill] = -1e9f;
                        outE[base + fill] = (float)v;
                        g_last[c * KK + fill] = v;
                        fill++;
                    }
                }
            }
        }

        if (t < NIT - 1) { bargen += NB; gridsync(bargen); }
    }
}

// ---------------- launch ----------------
extern "C" void kernel_launch(void* const* d_in, const int* in_sizes, int n_in,
                              void* d_out, int out_size) {
    const float* es    = (const float*)d_in[0];
    const int*   edges = (const int*)d_in[1];
    const int*   seeds = (const int*)d_in[2];
    const float* W     = (const float*)d_in[3];
    (void)n_in; (void)out_size;

    int e = in_sizes[1] / 2;
    const int* src = edges;
    const int* dst = edges + e;

    float* out  = (float*)d_out;
    float* outP = out;
    float* outE = out + NIT * CC * KK;
    float* outH = out + 2 * NIT * CC * KK;

    k_init<<<128, 256>>>();
    k_main<<<NB, 1024>>>(es, W, seeds, src, dst, e, outP, outE, outH);
}